// round 5
// baseline (speedup 1.0000x reference)
#include <cuda_runtime.h>
#include <cuda_bf16.h>
#include <stdint.h>

// ----------------------------------------------------------------------------
// SpectralPooling via HMMA (mma.sync m16n8k16 bf16, 3-term split) GEMMs.
// y = idctn(pad(crop(dctn(x)))); axes 0,1 cancel. Per-axis operator
// B[o][i] = sum_{k<28} D32[k,o]*D64[k,i]  (32x64), applied along axes 2,3,4.
//
// fused12: per CTA (b, i0-pair): load 2 slices X[b][i0][:][:] (64x64),
//   GEMM1 contracts i2 -> P[(s,i1)][o2]; split P to bf16 hi/lo, restage as
//   P^T[s*32+o2][i1] in smem; GEMM2 (A = Bmat rows=o1, B-op = P^T) contracts
//   i1 -> W[o1][o2] per slice; store g_W[b][o1*32+o2][i0] (float2 per i0-pair).
// stage3: GEMM over rows m=(b,col): K=i0 contiguous in g_W -> Y[b][o0][col].
// Precision: D = Ah*Bh + Ah*Bl + Al*Bh (bf16 hi/lo splits, fp32 accumulate).
// ----------------------------------------------------------------------------

__device__ __nv_bfloat16 g_Bh[2048];   // B hi, row-major [o][i] (32x64)
__device__ __nv_bfloat16 g_Bl[2048];   // B lo
__device__ float g_W[16777216];        // 64 MB scratch: [b][col][i0]

// ---------------- init: B and its bf16 hi/lo split -----------------------------
__global__ void init_B_kernel() {
    int idx = blockIdx.x * blockDim.x + threadIdx.x;
    if (idx >= 2048) return;
    int o = idx >> 6;   // 0..31
    int i = idx & 63;   // 0..63
    const float s32_0 = 0.17677669529663688f;  // sqrt(1/32)
    const float s32_k = 0.25f;                 // sqrt(2/32)
    const float s64_0 = 0.125f;                // sqrt(1/64)
    const float s64_k = 0.17677669529663688f;  // sqrt(2/64)
    float s = 0.0f;
    #pragma unroll
    for (int k = 0; k < 28; ++k) {
        float a32 = (2.0f * o + 1.0f) * (float)k / 64.0f;
        float a64 = (2.0f * i + 1.0f) * (float)k / 128.0f;
        float d32 = ((k == 0) ? s32_0 : s32_k) * cospif(a32);
        float d64 = ((k == 0) ? s64_0 : s64_k) * cospif(a64);
        s += d32 * d64;
    }
    __nv_bfloat16 h = __float2bfloat16(s);
    float lo = s - __bfloat162float(h);
    g_Bh[idx] = h;
    g_Bl[idx] = __float2bfloat16(lo);
}

// ---------------- mma.sync wrapper ----------------------------------------------
__device__ __forceinline__ void mma16816(float* d, const uint32_t* a,
                                         const uint32_t* b) {
    asm("mma.sync.aligned.m16n8k16.row.col.f32.bf16.bf16.f32 "
        "{%0,%1,%2,%3}, {%4,%5,%6,%7}, {%8,%9}, {%0,%1,%2,%3};"
        : "+f"(d[0]), "+f"(d[1]), "+f"(d[2]), "+f"(d[3])
        : "r"(a[0]), "r"(a[1]), "r"(a[2]), "r"(a[3]), "r"(b[0]), "r"(b[1]));
}

__device__ __forceinline__ void split_bf16(float v, __nv_bfloat16& h,
                                           __nv_bfloat16& l) {
    h = __float2bfloat16(v);
    l = __float2bfloat16(v - __bfloat162float(h));
}

// ---------------- fused stage 1+2 -------------------------------------------------
__global__ __launch_bounds__(128) void fused12(const float* __restrict__ x) {
    const int i0p = blockIdx.x;   // 0..31
    const int b   = blockIdx.y;   // 0..255

    // smem arena: [0,18432) A-hi (128x72 bf16)  | alias: P^T hi (64x72) + P^T lo
    //             [18432,36864) A-lo             | alias: ep fp32 2*32*33
    //             [36864,41472) B-hi (32x72)
    //             [41472,46080) B-lo
    __shared__ __align__(16) char arena[46080];
    __nv_bfloat16* sAh = (__nv_bfloat16*)(arena);
    __nv_bfloat16* sAl = (__nv_bfloat16*)(arena + 18432);
    __nv_bfloat16* sBh = (__nv_bfloat16*)(arena + 36864);
    __nv_bfloat16* sBl = (__nv_bfloat16*)(arena + 41472);
    __nv_bfloat16* sPh = (__nv_bfloat16*)(arena);            // 64x72
    __nv_bfloat16* sPl = (__nv_bfloat16*)(arena + 9216);     // 64x72
    float*         ep  = (float*)(arena + 18432);            // [2][32*33]

    const int tid = threadIdx.x;
    const int w   = tid >> 5;
    const int lid = tid & 31;
    const int gid = lid >> 2;   // 0..7
    const int tg  = lid & 3;    // 0..3

    // ---- load B hi/lo into padded smem (row stride 72 bf16)
    {
        const uint32_t* bh = (const uint32_t*)g_Bh;
        const uint32_t* bl = (const uint32_t*)g_Bl;
        #pragma unroll
        for (int idx = tid; idx < 1024; idx += 128) {
            int r = idx >> 5, c2 = idx & 31;
            *(uint32_t*)&sBh[r * 72 + c2 * 2] = bh[idx];
            *(uint32_t*)&sBl[r * 72 + c2 * 2] = bl[idx];
        }
    }

    // ---- load A tile (2 slices = 8192 floats), split hi/lo
    {
        const float4* __restrict__ inp =
            (const float4*)(x + (size_t)b * 262144 + (size_t)i0p * 8192);
        #pragma unroll
        for (int j = 0; j < 16; ++j) {
            int f = j * 128 + tid;           // float4 index 0..2047
            float4 v = inp[f];
            int r = f >> 4, k4 = f & 15;
            uint32_t h01, h23, l01, l23;
            asm("cvt.rn.bf16x2.f32 %0, %1, %2;" : "=r"(h01) : "f"(v.y), "f"(v.x));
            asm("cvt.rn.bf16x2.f32 %0, %1, %2;" : "=r"(h23) : "f"(v.w), "f"(v.z));
            float hx = __uint_as_float(h01 << 16);
            float hy = __uint_as_float(h01 & 0xFFFF0000u);
            float hz = __uint_as_float(h23 << 16);
            float hw = __uint_as_float(h23 & 0xFFFF0000u);
            asm("cvt.rn.bf16x2.f32 %0, %1, %2;" : "=r"(l01)
                : "f"(v.y - hy), "f"(v.x - hx));
            asm("cvt.rn.bf16x2.f32 %0, %1, %2;" : "=r"(l23)
                : "f"(v.w - hw), "f"(v.z - hz));
            *(uint2*)&sAh[r * 72 + k4 * 4] = make_uint2(h01, h23);
            *(uint2*)&sAl[r * 72 + k4 * 4] = make_uint2(l01, l23);
        }
    }
    __syncthreads();

    // ---- GEMM1: P[r][c] = sum_k A[r][k] B[c][k], M=128, N=32, K=64
    float acc[2][4][4];
    #pragma unroll
    for (int rt = 0; rt < 2; ++rt)
        #pragma unroll
        for (int nt = 0; nt < 4; ++nt)
            #pragma unroll
            for (int q = 0; q < 4; ++q) acc[rt][nt][q] = 0.0f;

    #pragma unroll
    for (int kk = 0; kk < 4; ++kk) {
        uint32_t ah[2][4], al[2][4];
        #pragma unroll
        for (int rt = 0; rt < 2; ++rt) {
            int row = w * 32 + rt * 16 + gid;
            const __nv_bfloat16* pH = sAh + row * 72 + kk * 16 + tg * 2;
            const __nv_bfloat16* pL = sAl + row * 72 + kk * 16 + tg * 2;
            ah[rt][0] = *(const uint32_t*)(pH);
            ah[rt][1] = *(const uint32_t*)(pH + 8 * 72);
            ah[rt][2] = *(const uint32_t*)(pH + 8);
            ah[rt][3] = *(const uint32_t*)(pH + 8 * 72 + 8);
            al[rt][0] = *(const uint32_t*)(pL);
            al[rt][1] = *(const uint32_t*)(pL + 8 * 72);
            al[rt][2] = *(const uint32_t*)(pL + 8);
            al[rt][3] = *(const uint32_t*)(pL + 8 * 72 + 8);
        }
        uint32_t bh[4][2], bl[4][2];
        #pragma unroll
        for (int nt = 0; nt < 4; ++nt) {
            int n = nt * 8 + gid;
            const __nv_bfloat16* pH = sBh + n * 72 + kk * 16 + tg * 2;
            const __nv_bfloat16* pL = sBl + n * 72 + kk * 16 + tg * 2;
            bh[nt][0] = *(const uint32_t*)(pH);
            bh[nt][1] = *(const uint32_t*)(pH + 8);
            bl[nt][0] = *(const uint32_t*)(pL);
            bl[nt][1] = *(const uint32_t*)(pL + 8);
        }
        #pragma unroll
        for (int rt = 0; rt < 2; ++rt)
            #pragma unroll
            for (int nt = 0; nt < 4; ++nt) {
                mma16816(acc[rt][nt], ah[rt], bh[nt]);
                mma16816(acc[rt][nt], ah[rt], bl[nt]);
                mma16816(acc[rt][nt], al[rt], bh[nt]);
            }
    }
    __syncthreads();   // A buffers dead; safe to write P^T into alias

    // ---- restage P^T[s*32+o2][i1] as bf16 hi/lo
    #pragma unroll
    for (int rt = 0; rt < 2; ++rt)
        #pragma unroll
        for (int nt = 0; nt < 4; ++nt)
            #pragma unroll
            for (int q = 0; q < 4; ++q) {
                int r = w * 32 + rt * 16 + gid + ((q >> 1) << 3);
                int c = nt * 8 + tg * 2 + (q & 1);
                int s = r >> 6, k = r & 63;
                __nv_bfloat16 h, l;
                split_bf16(acc[rt][nt][q], h, l);
                sPh[(s * 32 + c) * 72 + k] = h;
                sPl[(s * 32 + c) * 72 + k] = l;
            }
    __syncthreads();

    // ---- GEMM2: W[o1][o2] = sum_k Bmat[o1][k] P^T[o2][k]; M=64 (2 slices x 32 o1)
    const int s2  = w >> 1;
    const int o1b = (w & 1) * 16;
    float acc2[4][4];
    #pragma unroll
    for (int nt = 0; nt < 4; ++nt)
        #pragma unroll
        for (int q = 0; q < 4; ++q) acc2[nt][q] = 0.0f;

    #pragma unroll
    for (int kk = 0; kk < 4; ++kk) {
        uint32_t ah[4], al[4];
        {
            int row = o1b + gid;
            const __nv_bfloat16* pH = sBh + row * 72 + kk * 16 + tg * 2;
            const __nv_bfloat16* pL = sBl + row * 72 + kk * 16 + tg * 2;
            ah[0] = *(const uint32_t*)(pH);
            ah[1] = *(const uint32_t*)(pH + 8 * 72);
            ah[2] = *(const uint32_t*)(pH + 8);
            ah[3] = *(const uint32_t*)(pH + 8 * 72 + 8);
            al[0] = *(const uint32_t*)(pL);
            al[1] = *(const uint32_t*)(pL + 8 * 72);
            al[2] = *(const uint32_t*)(pL + 8);
            al[3] = *(const uint32_t*)(pL + 8 * 72 + 8);
        }
        uint32_t bh[4][2], bl[4][2];
        #pragma unroll
        for (int nt = 0; nt < 4; ++nt) {
            int n = s2 * 32 + nt * 8 + gid;
            const __nv_bfloat16* pH = sPh + n * 72 + kk * 16 + tg * 2;
            const __nv_bfloat16* pL = sPl + n * 72 + kk * 16 + tg * 2;
            bh[nt][0] = *(const uint32_t*)(pH);
            bh[nt][1] = *(const uint32_t*)(pH + 8);
            bl[nt][0] = *(const uint32_t*)(pL);
            bl[nt][1] = *(const uint32_t*)(pL + 8);
        }
        #pragma unroll
        for (int nt = 0; nt < 4; ++nt) {
            mma16816(acc2[nt], ah, bh[nt]);
            mma16816(acc2[nt], ah, bl[nt]);
            mma16816(acc2[nt], al, bh[nt]);
        }
    }

    // ---- epilogue: stage W[s][o1][o2] in fp32 smem (ep aliases sAl region)
    #pragma unroll
    for (int nt = 0; nt < 4; ++nt)
        #pragma unroll
        for (int q = 0; q < 4; ++q) {
            int r = o1b + gid + ((q >> 1) << 3);       // o1
            int c = nt * 8 + tg * 2 + (q & 1);         // o2
            ep[s2 * 1056 + r * 33 + c] = acc2[nt][q];
        }
    __syncthreads();

    // ---- store g_W[b][col][i0]: float2 per (col, i0-pair)
    {
        float* __restrict__ wb = g_W + ((size_t)b * 1024) * 64 + (size_t)(i0p * 2);
        #pragma unroll
        for (int j = 0; j < 8; ++j) {
            int col = j * 128 + tid;   // 0..1023
            int eidx = (col >> 5) * 33 + (col & 31);
            float2 v = make_float2(ep[eidx], ep[1056 + eidx]);
            *(float2*)(wb + (size_t)col * 64) = v;
        }
    }
}

// ---------------- stage 3: contract i0 --------------------------------------------
// rows m = b*1024 + col, K = i0 contiguous in g_W; out Y[b][o0][col].
__global__ __launch_bounds__(128) void stage3(float* __restrict__ out) {
    __shared__ __align__(16) __nv_bfloat16 sAh[128 * 72];
    __shared__ __align__(16) __nv_bfloat16 sAl[128 * 72];
    __shared__ __align__(16) __nv_bfloat16 sBh[32 * 72];
    __shared__ __align__(16) __nv_bfloat16 sBl[32 * 72];

    const int tid = threadIdx.x;
    const int w   = tid >> 5;
    const int lid = tid & 31;
    const int gid = lid >> 2;
    const int tg  = lid & 3;

    {
        const uint32_t* bh = (const uint32_t*)g_Bh;
        const uint32_t* bl = (const uint32_t*)g_Bl;
        #pragma unroll
        for (int idx = tid; idx < 1024; idx += 128) {
            int r = idx >> 5, c2 = idx & 31;
            *(uint32_t*)&sBh[r * 72 + c2 * 2] = bh[idx];
            *(uint32_t*)&sBl[r * 72 + c2 * 2] = bl[idx];
        }
    }
    {
        const float4* __restrict__ inp =
            (const float4*)(g_W + (size_t)blockIdx.x * 8192);
        #pragma unroll
        for (int j = 0; j < 16; ++j) {
            int f = j * 128 + tid;
            float4 v = inp[f];
            int r = f >> 4, k4 = f & 15;
            uint32_t h01, h23, l01, l23;
            asm("cvt.rn.bf16x2.f32 %0, %1, %2;" : "=r"(h01) : "f"(v.y), "f"(v.x));
            asm("cvt.rn.bf16x2.f32 %0, %1, %2;" : "=r"(h23) : "f"(v.w), "f"(v.z));
            float hx = __uint_as_float(h01 << 16);
            float hy = __uint_as_float(h01 & 0xFFFF0000u);
            float hz = __uint_as_float(h23 << 16);
            float hw = __uint_as_float(h23 & 0xFFFF0000u);
            asm("cvt.rn.bf16x2.f32 %0, %1, %2;" : "=r"(l01)
                : "f"(v.y - hy), "f"(v.x - hx));
            asm("cvt.rn.bf16x2.f32 %0, %1, %2;" : "=r"(l23)
                : "f"(v.w - hw), "f"(v.z - hz));
            *(uint2*)&sAh[r * 72 + k4 * 4] = make_uint2(h01, h23);
            *(uint2*)&sAl[r * 72 + k4 * 4] = make_uint2(l01, l23);
        }
    }
    __syncthreads();

    float acc[2][4][4];
    #pragma unroll
    for (int rt = 0; rt < 2; ++rt)
        #pragma unroll
        for (int nt = 0; nt < 4; ++nt)
            #pragma unroll
            for (int q = 0; q < 4; ++q) acc[rt][nt][q] = 0.0f;

    #pragma unroll
    for (int kk = 0; kk < 4; ++kk) {
        uint32_t ah[2][4], al[2][4];
        #pragma unroll
        for (int rt = 0; rt < 2; ++rt) {
            int row = w * 32 + rt * 16 + gid;
            const __nv_bfloat16* pH = sAh + row * 72 + kk * 16 + tg * 2;
            const __nv_bfloat16* pL = sAl + row * 72 + kk * 16 + tg * 2;
            ah[rt][0] = *(const uint32_t*)(pH);
            ah[rt][1] = *(const uint32_t*)(pH + 8 * 72);
            ah[rt][2] = *(const uint32_t*)(pH + 8);
            ah[rt][3] = *(const uint32_t*)(pH + 8 * 72 + 8);
            al[rt][0] = *(const uint32_t*)(pL);
            al[rt][1] = *(const uint32_t*)(pL + 8 * 72);
            al[rt][2] = *(const uint32_t*)(pL + 8);
            al[rt][3] = *(const uint32_t*)(pL + 8 * 72 + 8);
        }
        uint32_t bh[4][2], bl[4][2];
        #pragma unroll
        for (int nt = 0; nt < 4; ++nt) {
            int n = nt * 8 + gid;
            const __nv_bfloat16* pH = sBh + n * 72 + kk * 16 + tg * 2;
            const __nv_bfloat16* pL = sBl + n * 72 + kk * 16 + tg * 2;
            bh[nt][0] = *(const uint32_t*)(pH);
            bh[nt][1] = *(const uint32_t*)(pH + 8);
            bl[nt][0] = *(const uint32_t*)(pL);
            bl[nt][1] = *(const uint32_t*)(pL + 8);
        }
        #pragma unroll
        for (int rt = 0; rt < 2; ++rt)
            #pragma unroll
            for (int nt = 0; nt < 4; ++nt) {
                mma16816(acc[rt][nt], ah[rt], bh[nt]);
                mma16816(acc[rt][nt], ah[rt], bl[nt]);
                mma16816(acc[rt][nt], al[rt], bh[nt]);
            }
    }

    // epilogue: transpose through this warp's own (dead) A region
    __syncwarp();
    float* epw = (float*)(sAh + (size_t)w * 32 * 72);   // 32x33 fp32 fits
    #pragma unroll
    for (int rt = 0; rt < 2; ++rt)
        #pragma unroll
        for (int nt = 0; nt < 4; ++nt) {
            int r0 = rt * 16 + gid;
            int c0 = nt * 8 + tg * 2;
            epw[r0 * 33 + c0]           = acc[rt][nt][0];
            epw[r0 * 33 + c0 + 1]       = acc[rt][nt][1];
            epw[(r0 + 8) * 33 + c0]     = acc[rt][nt][2];
            epw[(r0 + 8) * 33 + c0 + 1] = acc[rt][nt][3];
        }
    __syncwarp();

    // coalesced transposed store: out[(m>>10)*32768 + c*1024 + (m&1023)]
    size_t m = (size_t)blockIdx.x * 128 + (size_t)(w * 32 + lid);
    float* __restrict__ ob = out + (m >> 10) * 32768 + (m & 1023);
    #pragma unroll
    for (int c = 0; c < 32; ++c)
        ob[(size_t)c << 10] = epw[lid * 33 + c];
}

// ---------------- launch ---------------------------------------------------------
extern "C" void kernel_launch(void* const* d_in, const int* in_sizes, int n_in,
                              void* d_out, int out_size) {
    const float* x = (const float*)d_in[0];
    float* out = (float*)d_out;

    init_B_kernel<<<16, 128>>>();

    dim3 g12(32, 256);
    fused12<<<g12, 128>>>(x);       // X -> g_W[b][col][i0]
    stage3<<<2048, 128>>>(out);     // g_W -> Y
}

// round 6
// speedup vs baseline: 1.1336x; 1.1336x over previous
#include <cuda_runtime.h>
#include <cuda_bf16.h>
#include <stdint.h>

// ----------------------------------------------------------------------------
// SpectralPooling via HMMA (mma.sync m16n8k16 bf16, 3-term split) GEMMs.
// y = idctn(pad(crop(dctn(x)))); axes 0,1 cancel. Per-axis operator
// B[o][i] = sum_{k<28} D32[k,o]*D64[k,i]  (32x64), applied along axes 2,3,4.
// Three stages, each GEMM [rows x 64] -> [rows x 32] against B^T; outputs are
// written "pre-transposed" so K is always contiguous and stores coalesce:
//   stage1 (SB=12): X[b][i0][i1][i2]   -> T1[b][o2][i0][i1]
//   stage2 (SB=11): T1[b][o2][i0][i1]  -> T2[b][o1][o2][i0]
//   stage3 (SB=10): T2[b][o1][o2][i0]  -> Y[b][o0][o1][o2]
// out_addr(m,c) = (m>>SB)*(32<<SB) + c*(1<<SB) + (m & ((1<<SB)-1))
// Precision: D = Ah*Bh + Ah*Bl + Al*Bh (bf16 hi/lo splits, fp32 accumulate).
// Fragments loaded with ldmatrix.x4 (4x fewer L1 instructions than LDS.32).
// ----------------------------------------------------------------------------

__device__ __nv_bfloat16 g_Bh[2048];   // B hi, row-major [o][i] (32x64)
__device__ __nv_bfloat16 g_Bl[2048];   // B lo
__device__ float g_T1[33554432];       // 128 MB scratch
__device__ float g_T2[16777216];       //  64 MB scratch

__device__ __forceinline__ uint32_t smem_u32(const void* p) {
    uint32_t a;
    asm("{ .reg .u64 t; cvta.to.shared.u64 t, %1; cvt.u32.u64 %0, t; }"
        : "=r"(a) : "l"(p));
    return a;
}

// ---------------- init: one warp per B element, lane = k-term -------------------
__global__ void init_B_kernel() {
    int gw   = (blockIdx.x * blockDim.x + threadIdx.x) >> 5;  // 0..2047
    int lane = threadIdx.x & 31;
    if (gw >= 2048) return;
    int o = gw >> 6;   // 0..31
    int i = gw & 63;   // 0..63
    float term = 0.0f;
    if (lane < 28) {
        const float s32_0 = 0.17677669529663688f;  // sqrt(1/32)
        const float s32_k = 0.25f;                 // sqrt(2/32)
        const float s64_0 = 0.125f;                // sqrt(1/64)
        const float s64_k = 0.17677669529663688f;  // sqrt(2/64)
        float a32 = (2.0f * o + 1.0f) * (float)lane / 64.0f;
        float a64 = (2.0f * i + 1.0f) * (float)lane / 128.0f;
        float d32 = ((lane == 0) ? s32_0 : s32_k) * cospif(a32);
        float d64 = ((lane == 0) ? s64_0 : s64_k) * cospif(a64);
        term = d32 * d64;
    }
    #pragma unroll
    for (int s = 16; s > 0; s >>= 1)
        term += __shfl_xor_sync(0xFFFFFFFFu, term, s);
    if (lane == 0) {
        __nv_bfloat16 h = __float2bfloat16(term);
        float lo = term - __bfloat162float(h);
        g_Bh[gw] = h;
        g_Bl[gw] = __float2bfloat16(lo);
    }
}

// ---------------- mma.sync / ldmatrix wrappers ------------------------------------
__device__ __forceinline__ void mma16816(float* d, const uint32_t* a,
                                         const uint32_t* b) {
    asm("mma.sync.aligned.m16n8k16.row.col.f32.bf16.bf16.f32 "
        "{%0,%1,%2,%3}, {%4,%5,%6,%7}, {%8,%9}, {%0,%1,%2,%3};"
        : "+f"(d[0]), "+f"(d[1]), "+f"(d[2]), "+f"(d[3])
        : "r"(a[0]), "r"(a[1]), "r"(a[2]), "r"(a[3]), "r"(b[0]), "r"(b[1]));
}

__device__ __forceinline__ void ldsm4(uint32_t* r, uint32_t addr) {
    asm volatile("ldmatrix.sync.aligned.m8n8.x4.shared.b16 {%0,%1,%2,%3}, [%4];"
                 : "=r"(r[0]), "=r"(r[1]), "=r"(r[2]), "=r"(r[3]) : "r"(addr));
}

// ---------------- stage kernel --------------------------------------------------
// A tile: 128 rows x 64 K (fp32 in, split to bf16 hi/lo in smem, stride 72 bf16).
// Warp w computes rows w*32..w*32+31, all 32 output cols.
template<int SB>
__global__ __launch_bounds__(128) void stage_kernel(const float* __restrict__ xin,
                                                    float* __restrict__ xout) {
    const float* in = (SB == 12) ? xin : (SB == 11 ? (const float*)g_T1
                                                   : (const float*)g_T2);
    float* out      = (SB == 12) ? (float*)g_T1
                                 : (SB == 11 ? (float*)g_T2 : xout);
    constexpr size_t OC = (size_t)1 << SB;

    __shared__ __align__(16) __nv_bfloat16 sAh[128 * 72];  // 18 KB
    __shared__ __align__(16) __nv_bfloat16 sAl[128 * 72];  // 18 KB
    __shared__ __align__(16) __nv_bfloat16 sBh[32 * 72];   // 4.5 KB
    __shared__ __align__(16) __nv_bfloat16 sBl[32 * 72];   // 4.5 KB

    const int tid = threadIdx.x;
    const int w   = tid >> 5;
    const int lid = tid & 31;
    const int gid = lid >> 2;   // 0..7
    const int tg  = lid & 3;    // 0..3

    // ---- load B hi/lo into padded smem (row stride 144 B)
    {
        const uint32_t* bh = (const uint32_t*)g_Bh;
        const uint32_t* bl = (const uint32_t*)g_Bl;
        #pragma unroll
        for (int idx = tid; idx < 1024; idx += 128) {
            int r = idx >> 5, c2 = idx & 31;
            *(uint32_t*)&sBh[r * 72 + c2 * 2] = bh[idx];
            *(uint32_t*)&sBl[r * 72 + c2 * 2] = bl[idx];
        }
    }

    // ---- load A tile (2048 float4), split to bf16 hi/lo, padded smem
    {
        const float4* __restrict__ inp =
            (const float4*)(in + (size_t)blockIdx.x * 8192);
        #pragma unroll
        for (int j = 0; j < 16; ++j) {
            int f = j * 128 + tid;           // float4 index 0..2047
            float4 v = inp[f];
            int r = f >> 4, k4 = f & 15;
            uint32_t h01, h23, l01, l23;
            asm("cvt.rn.bf16x2.f32 %0, %1, %2;" : "=r"(h01) : "f"(v.y), "f"(v.x));
            asm("cvt.rn.bf16x2.f32 %0, %1, %2;" : "=r"(h23) : "f"(v.w), "f"(v.z));
            float hx = __uint_as_float(h01 << 16);
            float hy = __uint_as_float(h01 & 0xFFFF0000u);
            float hz = __uint_as_float(h23 << 16);
            float hw = __uint_as_float(h23 & 0xFFFF0000u);
            asm("cvt.rn.bf16x2.f32 %0, %1, %2;" : "=r"(l01)
                : "f"(v.y - hy), "f"(v.x - hx));
            asm("cvt.rn.bf16x2.f32 %0, %1, %2;" : "=r"(l23)
                : "f"(v.w - hw), "f"(v.z - hz));
            *(uint2*)&sAh[r * 72 + k4 * 4] = make_uint2(h01, h23);
            *(uint2*)&sAl[r * 72 + k4 * 4] = make_uint2(l01, l23);
        }
    }
    __syncthreads();

    // ---- per-lane ldmatrix addressing
    // A (per rt, kk): matrices (mi&1 -> +8 rows, mi>>1 -> +8 k)
    // B (per t,  kk): matrices (mi>>1 -> +8 n,   mi&1  -> +8 k)
    const int lr = lid & 7, mi = lid >> 3;
    const uint32_t uAh = smem_u32(sAh), uAl = smem_u32(sAl);
    const uint32_t uBh = smem_u32(sBh), uBl = smem_u32(sBl);
    const uint32_t aoff0 =
        (uint32_t)(w * 32 + ((mi & 1) << 3) + lr) * 144u + ((mi >> 1) << 4);
    const uint32_t boff0 =
        (uint32_t)(((mi >> 1) << 3) + lr) * 144u + ((mi & 1) << 4);

    // ---- HMMA mainloop: acc[rt][nt][4]
    float acc[2][4][4];
    #pragma unroll
    for (int rt = 0; rt < 2; ++rt)
        #pragma unroll
        for (int nt = 0; nt < 4; ++nt)
            #pragma unroll
            for (int q = 0; q < 4; ++q) acc[rt][nt][q] = 0.0f;

    #pragma unroll
    for (int kk = 0; kk < 4; ++kk) {
        uint32_t ah[2][4], al[2][4];
        #pragma unroll
        for (int rt = 0; rt < 2; ++rt) {
            uint32_t ao = aoff0 + (uint32_t)(rt * 16 * 144) + (uint32_t)(kk * 32);
            ldsm4(ah[rt], uAh + ao);
            ldsm4(al[rt], uAl + ao);
        }
        // B: regs {b[2t][0], b[2t][1], b[2t+1][0], b[2t+1][1]} per ldsm4
        uint32_t bh[4][2], bl[4][2];
        #pragma unroll
        for (int t = 0; t < 2; ++t) {
            uint32_t bo = boff0 + (uint32_t)(t * 16 * 144) + (uint32_t)(kk * 32);
            uint32_t rh[4], rl[4];
            ldsm4(rh, uBh + bo);
            ldsm4(rl, uBl + bo);
            bh[2 * t][0] = rh[0]; bh[2 * t][1] = rh[1];
            bh[2 * t + 1][0] = rh[2]; bh[2 * t + 1][1] = rh[3];
            bl[2 * t][0] = rl[0]; bl[2 * t][1] = rl[1];
            bl[2 * t + 1][0] = rl[2]; bl[2 * t + 1][1] = rl[3];
        }
        #pragma unroll
        for (int rt = 0; rt < 2; ++rt)
            #pragma unroll
            for (int nt = 0; nt < 4; ++nt) {
                mma16816(acc[rt][nt], ah[rt], bh[nt]);   // Ah*Bh
                mma16816(acc[rt][nt], ah[rt], bl[nt]);   // Ah*Bl
                mma16816(acc[rt][nt], al[rt], bh[nt]);   // Al*Bh
            }
    }

    // ---- epilogue: transpose through this warp's own (dead) A region
    __syncwarp();
    float* epw = (float*)(sAh + (size_t)w * 32 * 72);   // 32x33 fp32 fits
    #pragma unroll
    for (int rt = 0; rt < 2; ++rt)
        #pragma unroll
        for (int nt = 0; nt < 4; ++nt) {
            int r0 = rt * 16 + gid;
            int c0 = nt * 8 + tg * 2;
            epw[r0 * 33 + c0]           = acc[rt][nt][0];
            epw[r0 * 33 + c0 + 1]       = acc[rt][nt][1];
            epw[(r0 + 8) * 33 + c0]     = acc[rt][nt][2];
            epw[(r0 + 8) * 33 + c0 + 1] = acc[rt][nt][3];
        }
    __syncwarp();

    // ---- coalesced transposed store
    size_t m = (size_t)blockIdx.x * 128 + (size_t)(w * 32 + lid);
    float* __restrict__ ob = out + (m >> SB) * (OC * 32) + (m & (OC - 1));
    #pragma unroll
    for (int c = 0; c < 32; ++c)
        ob[(size_t)c << SB] = epw[lid * 33 + c];
}

// ---------------- launch ---------------------------------------------------------
extern "C" void kernel_launch(void* const* d_in, const int* in_sizes, int n_in,
                              void* d_out, int out_size) {
    const float* x = (const float*)d_in[0];
    float* out = (float*)d_out;

    init_B_kernel<<<512, 128>>>();

    stage_kernel<12><<<8192, 128>>>(x, out);   // X  -> T1   (contract i2)
    stage_kernel<11><<<4096, 128>>>(x, out);   // T1 -> T2   (contract i1)
    stage_kernel<10><<<2048, 128>>>(x, out);   // T2 -> out  (contract i0)
}